// round 12
// baseline (speedup 1.0000x reference)
#include <cuda_runtime.h>
#include <math.h>

#define BB 64
#define NN 8192
#define WW 64
#define HH 4
#define CTRL 792   // H*(3W+6)
#define NT 64      // tiles per batch (NN / 128)

// ---------------- scratch (no allocation allowed) ----------------
__device__ float g_keys [BB*HH*WW];   // tanh(keys)
__device__ float g_erase[BB*HH*WW];   // sigmoid(erase)
__device__ float g_wvec [BB*HH*WW];   // tanh(write)
__device__ float g_params[BB*HH*8];   // beta,gate,s0,s1,s2,gamma,keynorm
__device__ float g_pmax [BB*HH*NT];   // per-tile score max
__device__ float g_psum [BB*HH*NT];   // per-tile sum exp(s - pmax)
__device__ float g_tp   [BB*HH*NT];   // per-tile sharpen partial sums
__device__ int   g_cnt1 [BB];
__device__ int   g_cnt2 [BB];

__device__ __forceinline__ float softplusf(float x){
    return x > 20.f ? x : log1pf(expf(x));
}
__device__ __forceinline__ float sigmoidf(float x){
    return 1.f/(1.f + expf(-x));
}

// ---------------- k0: control transforms + counter reset ----------------
__global__ void k0_controls(const float* __restrict__ ctrl){
    int bh = blockIdx.x;                 // b*4+h
    int b  = bh >> 2, h = bh & 3;
    int t  = threadIdx.x;                // 64 threads
    const float* c = ctrl + b*CTRL;

    if (t == 0 && bh < BB){ g_cnt1[bh] = 0; g_cnt2[bh] = 0; }

    float k = tanhf(c[h*WW + t]);
    g_keys [bh*WW + t] = k;
    g_erase[bh*WW + t] = sigmoidf(c[256 + h*WW + t]);
    g_wvec [bh*WW + t] = tanhf(c[512 + h*WW + t]);

    __shared__ float s2m[2];
    float sq = k*k;
    #pragma unroll
    for (int o = 16; o; o >>= 1) sq += __shfl_xor_sync(0xffffffffu, sq, o);
    if ((t & 31) == 0) s2m[t >> 5] = sq;
    __syncthreads();
    if (t == 0){
        float nrm   = sqrtf(s2m[0] + s2m[1]);
        float beta  = softplusf(c[768 + h]);
        float gate  = sigmoidf(c[772 + h]);
        float gamma = 1.f + softplusf(c[788 + h]);
        float a0 = c[776 + h*3 + 0], a1 = c[776 + h*3 + 1], a2 = c[776 + h*3 + 2];
        float m  = fmaxf(a0, fmaxf(a1, a2));
        float e0 = expf(a0 - m), e1 = expf(a1 - m), e2 = expf(a2 - m);
        float inv = 1.f/(e0 + e1 + e2);
        float* p = g_params + bh*8;
        p[0]=beta; p[1]=gate; p[2]=e0*inv; p[3]=e1*inv; p[4]=e2*inv; p[5]=gamma; p[6]=nrm;
    }
}

// ---------------- fused kernel: memory read ONCE ----------------
// block = (tile, b), 128 threads, tile = 128 memory rows held in SMEM throughout.
#define TP 17
__global__ __launch_bounds__(128) void kfused(const float* __restrict__ mem,
                                              const float* __restrict__ prev,
                                              float* __restrict__ out){
    int b    = blockIdx.y;
    int tile = blockIdx.x;
    int n0   = tile * 128;
    __shared__ float4 tileS[128*TP];        // 34816 B
    __shared__ float skey[HH*WW];           // 1024
    __shared__ float se[HH][WW], sv[HH][WW];// 2048
    __shared__ float sb[HH], skn[HH], sgate[HH], ss0[HH], ss1[HH], ss2[HH], sgam[HH];
    __shared__ float rmax[4][HH], rsum[4][HH], bmaxS[HH];
    __shared__ float sM[HH], sIS[HH];       // global softmax M, 1/S
    __shared__ float wi[HH][130];           // w_interp + halo
    __shared__ float wf[HH][128];           // unnormalized sharpened weights
    __shared__ float sInvT[HH];
    __shared__ float xred[4][HH];
    int t = threadIdx.x;
    int wid = t >> 5, lane = t & 31;

    skey[t]       = g_keys[b*HH*WW + t];
    skey[t + 128] = g_keys[b*HH*WW + t + 128];
    se[t >> 6][t & 63]          = g_erase[b*HH*WW + t];
    se[(t+128) >> 6][t & 63]    = g_erase[b*HH*WW + t + 128];
    sv[t >> 6][t & 63]          = g_wvec [b*HH*WW + t];
    sv[(t+128) >> 6][t & 63]    = g_wvec [b*HH*WW + t + 128];
    if (t < HH){
        const float* p = g_params + (b*HH + t)*8;
        sb[t]=p[0]; sgate[t]=p[1]; ss0[t]=p[2]; ss1[t]=p[3]; ss2[t]=p[4];
        sgam[t]=p[5]; skn[t]=p[6];
    }

    // ---- phase 1: the only DRAM read of memory ----
    const float4* gsrc = (const float4*)mem + ((size_t)b*NN + n0)*(WW/4);
    #pragma unroll
    for (int i = 0; i < 16; i++){
        int g = t + 128*i;
        tileS[(g >> 4)*TP + (g & 15)] = gsrc[g];
    }
    __syncthreads();

    const float4* mrow = tileS + t*TP;
    const float4* kk   = (const float4*)skey;
    float d0=0.f, d1=0.f, d2=0.f, d3=0.f, sq=0.f;
    #pragma unroll
    for (int j = 0; j < 16; j++){
        float4 m  = mrow[j];
        float4 c0 = kk[0*16 + j], c1 = kk[1*16 + j], c2 = kk[2*16 + j], c3 = kk[3*16 + j];
        sq += m.x*m.x + m.y*m.y + m.z*m.z + m.w*m.w;
        d0 += m.x*c0.x + m.y*c0.y + m.z*c0.z + m.w*c0.w;
        d1 += m.x*c1.x + m.y*c1.y + m.z*c1.z + m.w*c1.w;
        d2 += m.x*c2.x + m.y*c2.y + m.z*c2.z + m.w*c2.w;
        d3 += m.x*c3.x + m.y*c3.y + m.z*c3.z + m.w*c3.w;
    }
    float mn = sqrtf(sq);
    float s[HH];
    s[0] = sb[0]*d0/(skn[0]*mn + 1e-8f);
    s[1] = sb[1]*d1/(skn[1]*mn + 1e-8f);
    s[2] = sb[2]*d2/(skn[2]*mn + 1e-8f);
    s[3] = sb[3]*d3/(skn[3]*mn + 1e-8f);

    #pragma unroll
    for (int h = 0; h < HH; h++){
        float v = s[h];
        #pragma unroll
        for (int o = 16; o; o >>= 1) v = fmaxf(v, __shfl_xor_sync(0xffffffffu, v, o));
        if (lane == 0) rmax[wid][h] = v;
    }
    __syncthreads();
    if (t < HH)
        bmaxS[t] = fmaxf(fmaxf(rmax[0][t], rmax[1][t]), fmaxf(rmax[2][t], rmax[3][t]));
    __syncthreads();
    #pragma unroll
    for (int h = 0; h < HH; h++){
        float v = __expf(s[h] - bmaxS[h]);
        #pragma unroll
        for (int o = 16; o; o >>= 1) v += __shfl_xor_sync(0xffffffffu, v, o);
        if (lane == 0) rsum[wid][h] = v;
    }
    __syncthreads();
    if (t < HH){
        int idx = (b*HH + t)*NT + tile;
        g_pmax[idx] = bmaxS[t];
        g_psum[idx] = rsum[0][t] + rsum[1][t] + rsum[2][t] + rsum[3][t];
        __threadfence();
    }
    __syncthreads();
    if (t == 0){
        atomicAdd(&g_cnt1[b], 1);
        while (*(volatile int*)&g_cnt1[b] < NT) __nanosleep(200);
    }
    __syncthreads();

    // ---- combine global (M, 1/S); warp wid handles head wid ----
    {
        int base = (b*HH + wid)*NT;
        float pm0 = __ldcg(&g_pmax[base + lane]);
        float pm1 = __ldcg(&g_pmax[base + 32 + lane]);
        float ps0 = __ldcg(&g_psum[base + lane]);
        float ps1 = __ldcg(&g_psum[base + 32 + lane]);
        float m = fmaxf(pm0, pm1);
        #pragma unroll
        for (int o = 16; o; o >>= 1) m = fmaxf(m, __shfl_xor_sync(0xffffffffu, m, o));
        float ssum = ps0*__expf(pm0 - m) + ps1*__expf(pm1 - m);
        #pragma unroll
        for (int o = 16; o; o >>= 1) ssum += __shfl_xor_sync(0xffffffffu, ssum, o);
        if (lane == 0){ sM[wid] = m; sIS[wid] = 1.f/ssum; }
    }
    __syncthreads();

    // ---- w_interp own rows + halo rows ----
    const float* pr = prev + (size_t)b*HH*NN;
    #pragma unroll
    for (int h = 0; h < HH; h++){
        float pv = pr[(size_t)h*NN + n0 + t];
        wi[h][1 + t] = sgate[h]*(__expf(s[h] - sM[h])*sIS[h]) + (1.f - sgate[h])*pv;
    }
    if (wid < 2){   // warp0: left halo row, warp1: right halo row
        int hrow = (wid == 0) ? ((n0 + NN - 1) & (NN - 1)) : ((n0 + 128) & (NN - 1));
        const float* mr = mem + ((size_t)b*NN + hrow)*WW;
        float x0 = mr[lane], x1 = mr[32 + lane];
        float hsq = x0*x0 + x1*x1;
        float hd[HH];
        #pragma unroll
        for (int h = 0; h < HH; h++)
            hd[h] = x0*skey[h*WW + lane] + x1*skey[h*WW + 32 + lane];
        #pragma unroll
        for (int o = 16; o; o >>= 1){
            hsq   += __shfl_xor_sync(0xffffffffu, hsq,   o);
            hd[0] += __shfl_xor_sync(0xffffffffu, hd[0], o);
            hd[1] += __shfl_xor_sync(0xffffffffu, hd[1], o);
            hd[2] += __shfl_xor_sync(0xffffffffu, hd[2], o);
            hd[3] += __shfl_xor_sync(0xffffffffu, hd[3], o);
        }
        if (lane == 0){
            float hmn = sqrtf(hsq);
            #pragma unroll
            for (int h = 0; h < HH; h++){
                float sc = sb[h]*hd[h]/(skn[h]*hmn + 1e-8f);
                float wv = sgate[h]*(__expf(sc - sM[h])*sIS[h])
                         + (1.f - sgate[h])*pr[(size_t)h*NN + hrow];
                wi[h][(wid == 0) ? 0 : 129] = wv;
            }
        }
    }
    __syncthreads();

    // ---- sharpen + partial T ----
    float pw[HH];
    #pragma unroll
    for (int h = 0; h < HH; h++){
        float x = ss0[h]*wi[h][t] + ss1[h]*wi[h][t + 1] + ss2[h]*wi[h][t + 2];
        pw[h] = __powf(x, sgam[h]);
        wf[h][t] = pw[h];
    }
    #pragma unroll
    for (int h = 0; h < HH; h++){
        float v = pw[h];
        #pragma unroll
        for (int o = 16; o; o >>= 1) v += __shfl_xor_sync(0xffffffffu, v, o);
        if (lane == 0) xred[wid][h] = v;
    }
    __syncthreads();
    if (t < HH){
        g_tp[(b*HH + t)*NT + tile] = xred[0][t] + xred[1][t] + xred[2][t] + xred[3][t];
        __threadfence();
    }
    __syncthreads();
    if (t == 0){
        atomicAdd(&g_cnt2[b], 1);
        while (*(volatile int*)&g_cnt2[b] < NT) __nanosleep(200);
    }
    __syncthreads();

    {   // invT: warp wid handles head wid
        int base = (b*HH + wid)*NT;
        float a = __ldcg(&g_tp[base + lane]) + __ldcg(&g_tp[base + 32 + lane]);
        #pragma unroll
        for (int o = 16; o; o >>= 1) a += __shfl_xor_sync(0xffffffffu, a, o);
        if (lane == 0) sInvT[wid] = 1.f/(a + 1e-8f);
    }
    __syncthreads();

    // ---- phase 3: erase/add straight from the SMEM tile ----
    int l16 = t & 15, rg = t >> 4;   // 8 row-groups x 16 lanes
    float4 e0 = ((const float4*)se[0])[l16];
    float4 e1 = ((const float4*)se[1])[l16];
    float4 e2 = ((const float4*)se[2])[l16];
    float4 e3 = ((const float4*)se[3])[l16];
    float4 w0 = ((const float4*)sv[0])[l16];
    float4 w1 = ((const float4*)sv[1])[l16];
    float4 w2 = ((const float4*)sv[2])[l16];
    float4 w3 = ((const float4*)sv[3])[l16];
    float it0 = sInvT[0], it1 = sInvT[1], it2 = sInvT[2], it3 = sInvT[3];

    #pragma unroll
    for (int i = 0; i < 16; i++){
        int row = rg + 8*i;
        float a0 = wf[0][row]*it0, a1 = wf[1][row]*it1,
              a2 = wf[2][row]*it2, a3 = wf[3][row]*it3;
        float4 m = tileS[row*TP + l16];
        float4 o;
        o.x = m.x*(1.f-a0*e0.x)*(1.f-a1*e1.x)*(1.f-a2*e2.x)*(1.f-a3*e3.x)
            + a0*w0.x + a1*w1.x + a2*w2.x + a3*w3.x;
        o.y = m.y*(1.f-a0*e0.y)*(1.f-a1*e1.y)*(1.f-a2*e2.y)*(1.f-a3*e3.y)
            + a0*w0.y + a1*w1.y + a2*w2.y + a3*w3.y;
        o.z = m.z*(1.f-a0*e0.z)*(1.f-a1*e1.z)*(1.f-a2*e2.z)*(1.f-a3*e3.z)
            + a0*w0.z + a1*w1.z + a2*w2.z + a3*w3.z;
        o.w = m.w*(1.f-a0*e0.w)*(1.f-a1*e1.w)*(1.f-a2*e2.w)*(1.f-a3*e3.w)
            + a0*w0.w + a1*w1.w + a2*w2.w + a3*w3.w;
        __stcs((float4*)out + ((size_t)b*NN + n0 + row)*16 + l16, o);
    }
}

// ---------------- launch ----------------
extern "C" void kernel_launch(void* const* d_in, const int* in_sizes, int n_in,
                              void* d_out, int out_size) {
    const float* mem  = (const float*)d_in[0];   // [B,N,W]
    const float* ctrl = (const float*)d_in[1];   // [B,792]
    const float* prev = (const float*)d_in[2];   // [B,H,N]
    float* out = (float*)d_out;                  // [B,N,W]

    k0_controls<<<BB*HH, 64>>>(ctrl);
    kfused<<<dim3(NT, BB), 128>>>(mem, prev, out);
    (void)in_sizes; (void)n_in; (void)out_size;
}

// round 13
// speedup vs baseline: 1.2793x; 1.2793x over previous
#include <cuda_runtime.h>
#include <math.h>

#define BB 64
#define NN 8192
#define WW 64
#define HH 4
#define CTRL 792   // H*(3W+6)
#define K1TILES 64 // NN / K1_ROWSPB

// ---------------- scratch (no allocation allowed) ----------------
__device__ float g_keys [BB*HH*WW];   // tanh(keys)
__device__ float g_erase[BB*HH*WW];   // sigmoid(erase)
__device__ float g_wvec [BB*HH*WW];   // tanh(write)
__device__ float g_params[BB*HH*8];   // beta,gate,s0,s1,s2,gamma,keynorm
__device__ float g_scores[(size_t)BB*HH*NN];  // beta * cosine
__device__ float g_w     [(size_t)BB*HH*NN];  // UNNORMALIZED sharpened weights
__device__ float g_pmax [BB*HH*K1TILES];      // per-tile score max
__device__ float g_psum [BB*HH*K1TILES];      // per-tile sum exp(s - pmax)
__device__ float g_tpart[BB*HH*4];            // per-tile sharpen partial sums

__device__ __forceinline__ float softplusf(float x){
    return x > 20.f ? x : log1pf(expf(x));
}
__device__ __forceinline__ float sigmoidf(float x){
    return 1.f/(1.f + expf(-x));
}

// ---------------- k0: control transforms (tiny) ----------------
__global__ void k0_controls(const float* __restrict__ ctrl){
    int bh = blockIdx.x;                 // b*4+h
    int b  = bh >> 2, h = bh & 3;
    int t  = threadIdx.x;                // 64 threads
    const float* c = ctrl + b*CTRL;

    float k = tanhf(c[h*WW + t]);
    g_keys [bh*WW + t] = k;
    g_erase[bh*WW + t] = sigmoidf(c[256 + h*WW + t]);
    g_wvec [bh*WW + t] = tanhf(c[512 + h*WW + t]);

    __shared__ float s2m[2];
    float sq = k*k;
    #pragma unroll
    for (int o = 16; o; o >>= 1) sq += __shfl_xor_sync(0xffffffffu, sq, o);
    if ((t & 31) == 0) s2m[t >> 5] = sq;
    __syncthreads();
    if (t == 0){
        float nrm   = sqrtf(s2m[0] + s2m[1]);
        float beta  = softplusf(c[768 + h]);
        float gate  = sigmoidf(c[772 + h]);
        float gamma = 1.f + softplusf(c[788 + h]);
        float a0 = c[776 + h*3 + 0], a1 = c[776 + h*3 + 1], a2 = c[776 + h*3 + 2];
        float m  = fmaxf(a0, fmaxf(a1, a2));
        float e0 = expf(a0 - m), e1 = expf(a1 - m), e2 = expf(a2 - m);
        float inv = 1.f/(e0 + e1 + e2);
        float* p = g_params + bh*8;
        p[0]=beta; p[1]=gate; p[2]=e0*inv; p[3]=e1*inv; p[4]=e2*inv; p[5]=gamma; p[6]=nrm;
    }
}

// ---------------- k1: scores + per-tile softmax partials ----------------
// DEFAULT-cached loads: populate L2 so k3 (reversed order) can reuse the tail.
#define K1T 128
#define K1_ROWSPB 128
#define TP 17                     // row pitch in float4
__global__ __launch_bounds__(K1T) void k1_scores(const float* __restrict__ mem){
    int b  = blockIdx.y;
    int n0 = blockIdx.x * K1_ROWSPB;
    __shared__ float4 tile[K1_ROWSPB * TP];
    __shared__ float skey[HH*WW];
    __shared__ float sb[HH], skn[HH];
    __shared__ float rmax[4][HH], rsum[4][HH], bmax[HH];
    int t = threadIdx.x;
    skey[t]       = g_keys[b*HH*WW + t];
    skey[t + 128] = g_keys[b*HH*WW + t + 128];
    if (t < HH){ sb[t] = g_params[(b*HH + t)*8 + 0]; skn[t] = g_params[(b*HH + t)*8 + 6]; }

    const float4* gsrc = (const float4*)mem + ((size_t)b*NN + n0)*(WW/4);
    #pragma unroll
    for (int i = 0; i < 16; i++){
        int g = t + K1T*i;
        float4 v = gsrc[g];          // default policy: stays in L2
        tile[(g >> 4)*TP + (g & 15)] = v;
    }
    __syncthreads();

    const float4* mrow = tile + t*TP;
    const float4* kk   = (const float4*)skey;
    float d0 = 0.f, d1 = 0.f, d2 = 0.f, d3 = 0.f, sq = 0.f;
    #pragma unroll
    for (int j = 0; j < 16; j++){
        float4 m  = mrow[j];
        float4 c0 = kk[0*16 + j];
        float4 c1 = kk[1*16 + j];
        float4 c2 = kk[2*16 + j];
        float4 c3 = kk[3*16 + j];
        sq += m.x*m.x + m.y*m.y + m.z*m.z + m.w*m.w;
        d0 += m.x*c0.x + m.y*c0.y + m.z*c0.z + m.w*c0.w;
        d1 += m.x*c1.x + m.y*c1.y + m.z*c1.z + m.w*c1.w;
        d2 += m.x*c2.x + m.y*c2.y + m.z*c2.z + m.w*c2.w;
        d3 += m.x*c3.x + m.y*c3.y + m.z*c3.z + m.w*c3.w;
    }
    float mn  = sqrtf(sq);
    float s[HH];
    s[0] = sb[0]*d0/(skn[0]*mn + 1e-8f);
    s[1] = sb[1]*d1/(skn[1]*mn + 1e-8f);
    s[2] = sb[2]*d2/(skn[2]*mn + 1e-8f);
    s[3] = sb[3]*d3/(skn[3]*mn + 1e-8f);
    size_t base = (size_t)b*HH*NN + n0 + t;
    #pragma unroll
    for (int h = 0; h < HH; h++) g_scores[base + (size_t)h*NN] = s[h];

    int wid = t >> 5, lane = t & 31;
    #pragma unroll
    for (int h = 0; h < HH; h++){
        float v = s[h];
        #pragma unroll
        for (int o = 16; o; o >>= 1) v = fmaxf(v, __shfl_xor_sync(0xffffffffu, v, o));
        if (lane == 0) rmax[wid][h] = v;
    }
    __syncthreads();
    if (t < HH)
        bmax[t] = fmaxf(fmaxf(rmax[0][t], rmax[1][t]), fmaxf(rmax[2][t], rmax[3][t]));
    __syncthreads();
    #pragma unroll
    for (int h = 0; h < HH; h++){
        float v = __expf(s[h] - bmax[h]);
        #pragma unroll
        for (int o = 16; o; o >>= 1) v += __shfl_xor_sync(0xffffffffu, v, o);
        if (lane == 0) rsum[wid][h] = v;
    }
    __syncthreads();
    if (t < HH){
        int idx = (b*HH + t)*K1TILES + blockIdx.x;
        g_pmax[idx] = bmax[t];
        g_psum[idx] = rsum[0][t] + rsum[1][t] + rsum[2][t] + rsum[3][t];
    }
}

// ---------------- k2': tiled softmax-apply + interp + shift + sharpen ----------
#define K2B 256
#define K2TILE 2048
__global__ __launch_bounds__(K2B) void k2_weights(const float* __restrict__ prev){
    int blk  = blockIdx.x;
    int bh   = blk >> 2;
    int tilei= blk & 3;
    int t0   = tilei * K2TILE;
    __shared__ float wi[K2TILE + 2];
    __shared__ float sMS[2];
    __shared__ float red[K2B/32];
    int t = threadIdx.x;

    if (t < 32){
        float pm0 = g_pmax[bh*K1TILES + t];
        float pm1 = g_pmax[bh*K1TILES + t + 32];
        float ps0 = g_psum[bh*K1TILES + t];
        float ps1 = g_psum[bh*K1TILES + t + 32];
        float m = fmaxf(pm0, pm1);
        #pragma unroll
        for (int o = 16; o; o >>= 1) m = fmaxf(m, __shfl_xor_sync(0xffffffffu, m, o));
        float ss = ps0*__expf(pm0 - m) + ps1*__expf(pm1 - m);
        #pragma unroll
        for (int o = 16; o; o >>= 1) ss += __shfl_xor_sync(0xffffffffu, ss, o);
        if (t == 0){ sMS[0] = m; sMS[1] = 1.f/ss; }
    }

    const float* p = g_params + bh*8;
    float gate = p[1], s0 = p[2], s1 = p[3], s2 = p[4], gamma = p[5];
    const float* sc = g_scores + (size_t)bh*NN;
    const float* pr = prev     + (size_t)bh*NN;
    __syncthreads();
    float M = sMS[0], invS = sMS[1];

    float4 v0 = ((const float4*)(sc + t0))[t*2];
    float4 v1 = ((const float4*)(sc + t0))[t*2 + 1];
    float4 p0 = ((const float4*)(pr + t0))[t*2];
    float4 p1 = ((const float4*)(pr + t0))[t*2 + 1];
    float v[8]  = {v0.x, v0.y, v0.z, v0.w, v1.x, v1.y, v1.z, v1.w};
    float pv[8] = {p0.x, p0.y, p0.z, p0.w, p1.x, p1.y, p1.z, p1.w};
    #pragma unroll
    for (int j = 0; j < 8; j++)
        wi[1 + t*8 + j] = gate * (__expf(v[j] - M) * invS) + (1.f - gate) * pv[j];
    if (t == 0){
        int n = (t0 + NN - 1) & (NN - 1);
        wi[0] = gate * (__expf(sc[n] - M) * invS) + (1.f - gate) * pr[n];
    }
    if (t == 1){
        int n = (t0 + K2TILE) & (NN - 1);
        wi[K2TILE + 1] = gate * (__expf(sc[n] - M) * invS) + (1.f - gate) * pr[n];
    }
    __syncthreads();

    float pw[8];
    float ls = 0.f;
    #pragma unroll
    for (int j = 0; j < 8; j++){
        int l = t*8 + j;
        float x = s0*wi[l] + s1*wi[l + 1] + s2*wi[l + 2];
        pw[j] = __powf(x, gamma);
        ls += pw[j];
    }
    int lane = t & 31, wid = t >> 5;
    #pragma unroll
    for (int o = 16; o; o >>= 1) ls += __shfl_xor_sync(0xffffffffu, ls, o);
    if (lane == 0) red[wid] = ls;
    __syncthreads();
    if (t == 0){
        float a = red[0];
        #pragma unroll
        for (int k = 1; k < K2B/32; k++) a += red[k];
        g_tpart[bh*4 + tilei] = a;
    }

    float* wout = g_w + (size_t)bh*NN + t0;
    float4 o0 = {pw[0], pw[1], pw[2], pw[3]};
    float4 o1 = {pw[4], pw[5], pw[6], pw[7]};
    ((float4*)wout)[t*2]     = o0;
    ((float4*)wout)[t*2 + 1] = o1;
}

// ---------------- k3: erase/add update; REVERSED batch order for L2 tail reuse --
#define K3_ROWS 128
__global__ __launch_bounds__(256) void k3_out(const float* __restrict__ mem,
                                              float* __restrict__ out){
    int b  = (BB - 1) - blockIdx.y;      // reverse: hit k1's L2 tail first
    int n0 = blockIdx.x * K3_ROWS;
    __shared__ float se[HH][WW], sv[HH][WW];
    __shared__ float sa[HH][K3_ROWS];
    __shared__ float sInvT[HH];
    int t = threadIdx.x;
    se[t >> 6][t & 63] = g_erase[b*HH*WW + t];
    sv[t >> 6][t & 63] = g_wvec [b*HH*WW + t];
    if (t < HH){
        int base = (b*HH + t)*4;
        float T = g_tpart[base] + g_tpart[base+1] + g_tpart[base+2] + g_tpart[base+3];
        sInvT[t] = 1.f/(T + 1e-8f);
    }
    {
        int i0 = t, i1 = t + 256;
        sa[i0 >> 7][i0 & 127] = g_w[((size_t)b*HH + (i0 >> 7))*NN + n0 + (i0 & 127)];
        sa[i1 >> 7][i1 & 127] = g_w[((size_t)b*HH + (i1 >> 7))*NN + n0 + (i1 & 127)];
    }
    __syncthreads();

    int lane = t & 15, r = t >> 4;
    float4 e0 = ((const float4*)se[0])[lane];
    float4 e1 = ((const float4*)se[1])[lane];
    float4 e2 = ((const float4*)se[2])[lane];
    float4 e3 = ((const float4*)se[3])[lane];
    float4 w0 = ((const float4*)sv[0])[lane];
    float4 w1 = ((const float4*)sv[1])[lane];
    float4 w2 = ((const float4*)sv[2])[lane];
    float4 w3 = ((const float4*)sv[3])[lane];
    float it0 = sInvT[0], it1 = sInvT[1], it2 = sInvT[2], it3 = sInvT[3];

    size_t base = ((size_t)b*NN + n0 + r)*16 + lane;

    float4 m[8];
    #pragma unroll
    for (int i = 0; i < 8; i++)
        m[i] = __ldcs((const float4*)mem + base + (size_t)16*16*i);  // L2 hit→evict dead line

    #pragma unroll
    for (int i = 0; i < 8; i++){
        int rr = r + 16*i;
        float a0 = sa[0][rr]*it0, a1 = sa[1][rr]*it1,
              a2 = sa[2][rr]*it2, a3 = sa[3][rr]*it3;
        float4 o;
        o.x = m[i].x*(1.f-a0*e0.x)*(1.f-a1*e1.x)*(1.f-a2*e2.x)*(1.f-a3*e3.x)
            + a0*w0.x + a1*w1.x + a2*w2.x + a3*w3.x;
        o.y = m[i].y*(1.f-a0*e0.y)*(1.f-a1*e1.y)*(1.f-a2*e2.y)*(1.f-a3*e3.y)
            + a0*w0.y + a1*w1.y + a2*w2.y + a3*w3.y;
        o.z = m[i].z*(1.f-a0*e0.z)*(1.f-a1*e1.z)*(1.f-a2*e2.z)*(1.f-a3*e3.z)
            + a0*w0.z + a1*w1.z + a2*w2.z + a3*w3.z;
        o.w = m[i].w*(1.f-a0*e0.w)*(1.f-a1*e1.w)*(1.f-a2*e2.w)*(1.f-a3*e3.w)
            + a0*w0.w + a1*w1.w + a2*w2.w + a3*w3.w;
        __stcs((float4*)out + base + (size_t)16*16*i, o);   // don't evict mem lines
    }
}

// ---------------- launch ----------------
extern "C" void kernel_launch(void* const* d_in, const int* in_sizes, int n_in,
                              void* d_out, int out_size) {
    const float* mem  = (const float*)d_in[0];   // [B,N,W]
    const float* ctrl = (const float*)d_in[1];   // [B,792]
    const float* prev = (const float*)d_in[2];   // [B,H,N]
    float* out = (float*)d_out;                  // [B,N,W]

    k0_controls<<<BB*HH, 64>>>(ctrl);
    k1_scores  <<<dim3(NN/K1_ROWSPB, BB), K1T>>>(mem);
    k2_weights <<<BB*HH*4, K2B>>>(prev);
    k3_out     <<<dim3(NN/K3_ROWS, BB), 256>>>(mem, out);
    (void)in_sizes; (void)n_in; (void)out_size;
}